// round 13
// baseline (speedup 1.0000x reference)
#include <cuda_runtime.h>
#include <cstdint>

// x: (32,1,64,8000) fp32, a:(64,), w:(64,)
// y[b,f,t] = | x[t] - Cw * S_t |,  S_t = sum_{d=1}^{498} a^{d-1} x_edge[t-d]
// Cw = w*(1-a)/(1-a^498), edge pad x[j<0] -> x[0]
//
// One block per FIFTH of a row (1600 samples + 500 halo). TMA in/out,
// LSUB=20 chunked warm-up, float4-streamed B-phase, <=16KB smem so the
// 8KB-granule allocator packs 12 blocks/SM.
#define T_LEN   8000
#define TILE_T  1600
#define NTILES  5
#define HALO    500
#define XS_LEN  2100
#define WIN     498
#define LSUB    20
#define NSUB    80          // workers
#define NG      104         // chunk sums (NSUB + 24)
#define BLOCK   128
// float offsets in dynamic smem
#define OFF_XS   0
#define OFF_YS   2100
#define OFF_SG   3700
#define OFF_SHD  3804
#define OFF_MBAR 3908       // byte 15632: 16B-aligned
#define SMEM_BYTES (3908 * 4 + 16)   // 15648 B < 16 KB

__device__ __forceinline__ float ipowf(float base, int e) {
    float p = 1.0f;
    while (e) { if (e & 1) p *= base; base *= base; e >>= 1; }
    return p;
}

__device__ __forceinline__ void mbar_wait0(uint32_t mbar) {
    uint32_t done;
    asm volatile(
        "{\n\t.reg .pred p;\n\t"
        "mbarrier.try_wait.parity.shared.b64 p, [%1], 0;\n\t"
        "selp.b32 %0, 1, 0, p;\n\t}"
        : "=r"(done) : "r"(mbar) : "memory");
    while (!done) {
        asm volatile(
            "{\n\t.reg .pred p;\n\t"
            "mbarrier.try_wait.parity.shared.b64 p, [%1], 0, 0x989680;\n\t"
            "selp.b32 %0, 1, 0, p;\n\t}"
            : "=r"(done) : "r"(mbar) : "memory");
    }
}

__global__ __launch_bounds__(BLOCK, 12)
void willmore_kernel(const float* __restrict__ x,
                     const float* __restrict__ a,
                     const float* __restrict__ w,
                     float* __restrict__ out,
                     int F) {
    extern __shared__ float sm[];
    float*  xs  = sm + OFF_XS;
    float*  ys  = sm + OFF_YS;
    float*  sG  = sm + OFF_SG;
    float*  sHd = sm + OFF_SHD;
    float4* xs4 = (float4*)xs;
    const uint32_t mbar = (uint32_t)__cvta_generic_to_shared(sm + OFF_MBAR);

    const int tid    = threadIdx.x;
    const int row    = blockIdx.x / NTILES;
    const int seg    = blockIdx.x - row * NTILES;
    const int t_base = seg * TILE_T;
    const int f      = row % F;
    const float* __restrict__ xrow = x + (size_t)row * T_LEN;
    float*       __restrict__ orow = out + (size_t)row * T_LEN + t_base;

    if (tid == 0)
        asm volatile("mbarrier.init.shared.b64 [%0], 1;" :: "r"(mbar) : "memory");
    __syncthreads();

    // phase A: TMA load (+ halo splat for the first segment)
    if (tid == 0) {
        const int   nbytes = (seg == 0) ? TILE_T * 4 : XS_LEN * 4;
        const float* src   = (seg == 0) ? xrow : (xrow + t_base - HALO);
        uint32_t dst = (uint32_t)__cvta_generic_to_shared(
                           (seg == 0) ? (xs + HALO) : xs);
        asm volatile("mbarrier.arrive.expect_tx.shared.b64 _, [%0], %1;"
                     :: "r"(mbar), "r"(nbytes) : "memory");
        asm volatile(
            "cp.async.bulk.shared::cluster.global.mbarrier::complete_tx::bytes "
            "[%0], [%1], %2, [%3];"
            :: "r"(dst), "l"(src), "r"(nbytes), "r"(mbar) : "memory");
    }

    // constants overlap the DMA
    const float af = __ldg(&a[f]);
    const float wf = __ldg(&w[f]);
    const float p498 = ipowf(af, WIN);
    const float Cw = (1.0f - af) / (1.0f - p498) * wf;
    const float a9  = ipowf(af, 9);
    const float a18 = a9 * a9;
    const float a20 = a18 * af * af;
    const float a240 = ipowf(a20, 12);

    if (seg == 0) {
        const float x0v = __ldg(&xrow[0]);
        const float4 pad4 = make_float4(x0v, x0v, x0v, x0v);
        #pragma unroll
        for (int i = tid; i < HALO / 4; i += BLOCK)
            xs4[i] = pad4;   // disjoint from DMA destination
    }
    mbar_wait0(mbar);
    __syncthreads();   // splat + DMA visible to all

    // ---- B1: chunk sums over xs[20k+2 .. 20k+21] (two 9-chains + tail) ----
    // prefix p (18 terms) = pA * a^9 + pB ; G = (p*a + x20)*a + x21
    if (tid < NG) {
        const int b4 = 5 * tid;
        float4 q0 = xs4[b4];
        float4 q1 = xs4[b4 + 1];
        float4 q2 = xs4[b4 + 2];
        // pA: x[2..10] = q0.zw q1.xyzw q2.xyz
        float pA = q0.z;
        pA = fmaf(af, pA, q0.w);
        pA = fmaf(af, pA, q1.x); pA = fmaf(af, pA, q1.y);
        pA = fmaf(af, pA, q1.z); pA = fmaf(af, pA, q1.w);
        pA = fmaf(af, pA, q2.x); pA = fmaf(af, pA, q2.y);
        pA = fmaf(af, pA, q2.z);
        // pB: x[11..19] = q2.w q3.xyzw q4.xyzw
        float4 q3 = xs4[b4 + 3];
        float4 q4 = xs4[b4 + 4];
        float pB = q2.w;
        pB = fmaf(af, pB, q3.x); pB = fmaf(af, pB, q3.y);
        pB = fmaf(af, pB, q3.z); pB = fmaf(af, pB, q3.w);
        pB = fmaf(af, pB, q4.x); pB = fmaf(af, pB, q4.y);
        pB = fmaf(af, pB, q4.z); pB = fmaf(af, pB, q4.w);
        float g = fmaf(pA, a9, pB);
        sHd[tid] = g;                          // 18-term prefix
        float4 q5 = xs4[b4 + 5];
        g = fmaf(af, g, q5.x);
        g = fmaf(af, g, q5.y);
        sG[tid] = g;                           // full 20-term chunk sum
    }
    __syncthreads();

    // ---- B2: warm-up combine (two 12-chains) + sliding recurrence ----
    if (tid < NSUB) {
        // T = Horner over sG[tid..tid+23] (farthest first), base a^20
        float TA = sG[tid];
        float TB = sG[tid + 12];
        #pragma unroll
        for (int m = 1; m < 12; ++m) {
            TA = fmaf(a20, TA, sG[tid + m]);
            TB = fmaf(a20, TB, sG[tid + 12 + m]);
        }
        const float T = fmaf(TA, a240, TB);
        float S = fmaf(a18, T, sHd[tid + 24]);

        const int q0i = 5 * tid;               // float4 index of chunk start
        float4* ys4 = (float4*)ys;
        float4 mA = xs4[q0i];                  // own-chunk quad j
        #pragma unroll
        for (int j = 0; j < 5; ++j) {
            const float4 mB = xs4[q0i + j + 1];
            const float4 xt = xs4[125 + q0i + j];   // xs[500 + 20i + 4j ..]
            float4 yv;
            yv.x = fabsf(fmaf(-Cw, S, xt.x));
            S = fmaf(af, S, fmaf(-p498, mA.z, xt.x));
            yv.y = fabsf(fmaf(-Cw, S, xt.y));
            S = fmaf(af, S, fmaf(-p498, mA.w, xt.y));
            yv.z = fabsf(fmaf(-Cw, S, xt.z));
            S = fmaf(af, S, fmaf(-p498, mB.x, xt.z));
            yv.w = fabsf(fmaf(-Cw, S, xt.w));
            S = fmaf(af, S, fmaf(-p498, mB.y, xt.w));
            ys4[q0i + j] = yv;
            mA = mB;
        }
    }
    __syncthreads();

    // ---- phase C: contiguous TMA store; release smem when read is done ----
    if (tid == 0) {
        uint32_t src = (uint32_t)__cvta_generic_to_shared(ys);
        asm volatile("fence.proxy.async.shared::cta;" ::: "memory");
        asm volatile("cp.async.bulk.global.shared::cta.bulk_group [%0], [%1], %2;"
                     :: "l"(orow), "r"(src), "r"(TILE_T * 4) : "memory");
        asm volatile("cp.async.bulk.commit_group;" ::: "memory");
        asm volatile("cp.async.bulk.wait_group.read 0;" ::: "memory");
    }
}

extern "C" void kernel_launch(void* const* d_in, const int* in_sizes, int n_in,
                              void* d_out, int out_size) {
    const float* x = (const float*)d_in[0];
    const float* a = (const float*)d_in[1];
    const float* w = (const float*)d_in[2];
    float* out = (float*)d_out;

    const int F = in_sizes[1];                 // 64
    const int rows = in_sizes[0] / T_LEN;      // 2048

    cudaFuncSetAttribute(willmore_kernel,
                         cudaFuncAttributeMaxDynamicSharedMemorySize, SMEM_BYTES);
    willmore_kernel<<<rows * NTILES, BLOCK, SMEM_BYTES>>>(x, a, w, out, F);
}

// round 14
// speedup vs baseline: 1.0102x; 1.0102x over previous
#include <cuda_runtime.h>
#include <cstdint>

// x: (32,1,64,8000) fp32, a:(64,), w:(64,)
// y[b,f,t] = | x[t] - Cw * S_t |,  S_t = sum_{d=1}^{498} a^{d-1} x_edge[t-d]
// Cw = w*(1-a)/(1-a^498), edge pad x[j<0] -> x[0]
//
// One block per QUARTER row (2000 samples + 500 halo). TMA in/out.
// ALIGNED-WINDOW warm-up: S = W(500-term, quad-aligned) - p498*(x[t0-499]+a*x[t0-500]),
// so B1 reads exactly 5 aligned quads per chunk and no prefix array is needed.
#define T_LEN   8000
#define TILE_T  2000
#define HALO    500
#define XS_LEN  2500
#define WIN     498
#define LSUB    20
#define NSUB    100         // workers
#define NG      125         // aligned chunk sums (i..i+24 for i<=99)
#define BLOCK   128
// float offsets in dynamic smem
#define OFF_XS   0
#define OFF_YS   2500
#define OFF_SG   4500
#define OFF_MBAR 4628       // byte 18512: 16B-aligned
#define SMEM_BYTES (4628 * 4 + 16)

__device__ __forceinline__ float ipowf(float base, int e) {
    float p = 1.0f;
    while (e) { if (e & 1) p *= base; base *= base; e >>= 1; }
    return p;
}

__device__ __forceinline__ void mbar_wait0(uint32_t mbar) {
    uint32_t done;
    asm volatile(
        "{\n\t.reg .pred p;\n\t"
        "mbarrier.try_wait.parity.shared.b64 p, [%1], 0;\n\t"
        "selp.b32 %0, 1, 0, p;\n\t}"
        : "=r"(done) : "r"(mbar) : "memory");
    while (!done) {
        asm volatile(
            "{\n\t.reg .pred p;\n\t"
            "mbarrier.try_wait.parity.shared.b64 p, [%1], 0, 0x989680;\n\t"
            "selp.b32 %0, 1, 0, p;\n\t}"
            : "=r"(done) : "r"(mbar) : "memory");
    }
}

__global__ __launch_bounds__(BLOCK, 12)
void willmore_kernel(const float* __restrict__ x,
                     const float* __restrict__ a,
                     const float* __restrict__ w,
                     float* __restrict__ out,
                     int F) {
    extern __shared__ float sm[];
    float*  xs  = sm + OFF_XS;
    float*  ys  = sm + OFF_YS;
    float*  sG  = sm + OFF_SG;
    float4* xs4 = (float4*)xs;
    const uint32_t mbar = (uint32_t)__cvta_generic_to_shared(sm + OFF_MBAR);

    const int tid    = threadIdx.x;
    const int row    = blockIdx.x >> 2;
    const int quar   = blockIdx.x & 3;
    const int t_base = quar * TILE_T;
    const int f      = row % F;
    const float* __restrict__ xrow = x + (size_t)row * T_LEN;
    float*       __restrict__ orow = out + (size_t)row * T_LEN + t_base;

    if (tid == 0)
        asm volatile("mbarrier.init.shared.b64 [%0], 1;" :: "r"(mbar) : "memory");
    __syncthreads();

    // phase A: TMA load (+ halo splat for the first quarter)
    if (tid == 0) {
        const int   nbytes = (quar == 0) ? TILE_T * 4 : XS_LEN * 4;
        const float* src   = (quar == 0) ? xrow : (xrow + t_base - HALO);
        uint32_t dst = (uint32_t)__cvta_generic_to_shared(
                           (quar == 0) ? (xs + HALO) : xs);
        asm volatile("mbarrier.arrive.expect_tx.shared.b64 _, [%0], %1;"
                     :: "r"(mbar), "r"(nbytes) : "memory");
        asm volatile(
            "cp.async.bulk.shared::cluster.global.mbarrier::complete_tx::bytes "
            "[%0], [%1], %2, [%3];"
            :: "r"(dst), "l"(src), "r"(nbytes), "r"(mbar) : "memory");
    }

    // constants overlap the DMA
    const float af = __ldg(&a[f]);
    const float wf = __ldg(&w[f]);
    const float p498 = ipowf(af, WIN);
    const float Cw = (1.0f - af) / (1.0f - p498) * wf;
    const float a10 = ipowf(af, 10);
    const float a20 = a10 * a10;
    const float a240 = ipowf(a20, 12);

    if (quar == 0) {
        const float x0v = __ldg(&xrow[0]);
        const float4 pad4 = make_float4(x0v, x0v, x0v, x0v);
        #pragma unroll
        for (int i = tid; i < HALO / 4; i += BLOCK)
            xs4[i] = pad4;   // disjoint from DMA destination
    }
    mbar_wait0(mbar);
    __syncthreads();   // splat + DMA visible to all

    // ---- B1: ALIGNED chunk sums G_k = Horner20 over xs[20k..20k+19] ----
    // two 10-chains for latency: G = pA * a^10 + pB
    if (tid < NG) {
        const int b4 = 5 * tid;
        const float4 q0 = xs4[b4];
        const float4 q1 = xs4[b4 + 1];
        const float4 q2 = xs4[b4 + 2];
        const float4 q3 = xs4[b4 + 3];
        const float4 q4 = xs4[b4 + 4];
        float pA = q0.x;
        pA = fmaf(af, pA, q0.y); pA = fmaf(af, pA, q0.z); pA = fmaf(af, pA, q0.w);
        pA = fmaf(af, pA, q1.x); pA = fmaf(af, pA, q1.y);
        pA = fmaf(af, pA, q1.z); pA = fmaf(af, pA, q1.w);
        pA = fmaf(af, pA, q2.x); pA = fmaf(af, pA, q2.y);
        float pB = q2.z;
        pB = fmaf(af, pB, q2.w);
        pB = fmaf(af, pB, q3.x); pB = fmaf(af, pB, q3.y);
        pB = fmaf(af, pB, q3.z); pB = fmaf(af, pB, q3.w);
        pB = fmaf(af, pB, q4.x); pB = fmaf(af, pB, q4.y);
        pB = fmaf(af, pB, q4.z); pB = fmaf(af, pB, q4.w);
        sG[tid] = fmaf(pA, a10, pB);
    }
    __syncthreads();

    // ---- B2: combine (13+12 split Horner) + correction + recurrence ----
    if (tid < NSUB) {
        // W = Horner over sG[tid..tid+24], base a^20, farthest first
        float TA = sG[tid];
        float TB = sG[tid + 13];
        #pragma unroll
        for (int m = 1; m < 12; ++m) {
            TA = fmaf(a20, TA, sG[tid + m]);
            TB = fmaf(a20, TB, sG[tid + 13 + m]);
        }
        TA = fmaf(a20, TA, sG[tid + 12]);      // 13th term of TA
        const float W = fmaf(TA, a240, TB);

        const int q0i = 5 * tid;               // float4 index of window start
        float4* ys4 = (float4*)ys;
        float4 mA = xs4[q0i];                  // own-window quad 0
        // S = W - p498*(x[t0-499] + a*x[t0-500]) = W - p498*(mA.y + a*mA.x)
        float S = fmaf(-p498, fmaf(af, mA.x, mA.y), W);

        #pragma unroll
        for (int j = 0; j < 5; ++j) {
            const float4 mB = xs4[q0i + j + 1];
            const float4 xt = xs4[125 + q0i + j];   // xs[500 + 20i + 4j ..]
            float4 yv;
            yv.x = fabsf(fmaf(-Cw, S, xt.x));
            S = fmaf(af, S, fmaf(-p498, mA.z, xt.x));
            yv.y = fabsf(fmaf(-Cw, S, xt.y));
            S = fmaf(af, S, fmaf(-p498, mA.w, xt.y));
            yv.z = fabsf(fmaf(-Cw, S, xt.z));
            S = fmaf(af, S, fmaf(-p498, mB.x, xt.z));
            yv.w = fabsf(fmaf(-Cw, S, xt.w));
            S = fmaf(af, S, fmaf(-p498, mB.y, xt.w));
            ys4[q0i + j] = yv;
            mA = mB;
        }
    }
    __syncthreads();

    // ---- phase C: contiguous TMA store; release smem when read is done ----
    if (tid == 0) {
        uint32_t src = (uint32_t)__cvta_generic_to_shared(ys);
        asm volatile("fence.proxy.async.shared::cta;" ::: "memory");
        asm volatile("cp.async.bulk.global.shared::cta.bulk_group [%0], [%1], %2;"
                     :: "l"(orow), "r"(src), "r"(TILE_T * 4) : "memory");
        asm volatile("cp.async.bulk.commit_group;" ::: "memory");
        asm volatile("cp.async.bulk.wait_group.read 0;" ::: "memory");
    }
}

extern "C" void kernel_launch(void* const* d_in, const int* in_sizes, int n_in,
                              void* d_out, int out_size) {
    const float* x = (const float*)d_in[0];
    const float* a = (const float*)d_in[1];
    const float* w = (const float*)d_in[2];
    float* out = (float*)d_out;

    const int F = in_sizes[1];                 // 64
    const int rows = in_sizes[0] / T_LEN;      // 2048

    cudaFuncSetAttribute(willmore_kernel,
                         cudaFuncAttributeMaxDynamicSharedMemorySize, SMEM_BYTES);
    willmore_kernel<<<rows * 4, BLOCK, SMEM_BYTES>>>(x, a, w, out, F);
}

// round 15
// speedup vs baseline: 1.0463x; 1.0357x over previous
#include <cuda_runtime.h>
#include <cstdint>

// x: (32,1,64,8000) fp32, a:(64,), w:(64,)
// y[b,f,t] = | x[t] - Cw * S_t |,  S_t = sum_{d=1}^{498} a^{d-1} x_edge[t-d]
// Cw = w*(1-a)/(1-a^498), edge pad x[j<0] -> x[0]
//
// One block per QUARTER row (2000 samples + 500 halo). TMA in/out.
// Aligned-window warm-up with TWO-LEVEL combine:
//   sG[k]  = 20-term Horner of chunk k
//   sP[j]  = 5-chunk Horner of sG[j..j+4]     (base a^20)
//   W(i)   = 5-term Horner of sP[i..i+20:5]   (base a^100)
//   S      = W - p498*(x[t0-499] + a*x[t0-500])
#define T_LEN   8000
#define TILE_T  2000
#define HALO    500
#define XS_LEN  2500
#define WIN     498
#define LSUB    20
#define NSUB    100         // workers
#define NG      125         // aligned chunk sums
#define NP      121         // level-1 partials (sP[j] needs sG[j+4] <= 124)
#define BLOCK   128
// float offsets in dynamic smem
#define OFF_XS   0
#define OFF_YS   2500
#define OFF_SG   4500
#define OFF_SP   4625
#define OFF_MBAR 4748       // byte 18992: 16B-aligned
#define SMEM_BYTES (4748 * 4 + 16)

__device__ __forceinline__ float ipowf(float base, int e) {
    float p = 1.0f;
    while (e) { if (e & 1) p *= base; base *= base; e >>= 1; }
    return p;
}

__device__ __forceinline__ void mbar_wait0(uint32_t mbar) {
    uint32_t done;
    asm volatile(
        "{\n\t.reg .pred p;\n\t"
        "mbarrier.try_wait.parity.shared.b64 p, [%1], 0;\n\t"
        "selp.b32 %0, 1, 0, p;\n\t}"
        : "=r"(done) : "r"(mbar) : "memory");
    while (!done) {
        asm volatile(
            "{\n\t.reg .pred p;\n\t"
            "mbarrier.try_wait.parity.shared.b64 p, [%1], 0, 0x989680;\n\t"
            "selp.b32 %0, 1, 0, p;\n\t}"
            : "=r"(done) : "r"(mbar) : "memory");
    }
}

__global__ __launch_bounds__(BLOCK, 12)
void willmore_kernel(const float* __restrict__ x,
                     const float* __restrict__ a,
                     const float* __restrict__ w,
                     float* __restrict__ out,
                     int F) {
    extern __shared__ float sm[];
    float*  xs  = sm + OFF_XS;
    float*  ys  = sm + OFF_YS;
    float*  sG  = sm + OFF_SG;
    float*  sP  = sm + OFF_SP;
    float4* xs4 = (float4*)xs;
    const uint32_t mbar = (uint32_t)__cvta_generic_to_shared(sm + OFF_MBAR);

    const int tid    = threadIdx.x;
    const int row    = blockIdx.x >> 2;
    const int quar   = blockIdx.x & 3;
    const int t_base = quar * TILE_T;
    const int f      = row % F;
    const float* __restrict__ xrow = x + (size_t)row * T_LEN;
    float*       __restrict__ orow = out + (size_t)row * T_LEN + t_base;

    if (tid == 0)
        asm volatile("mbarrier.init.shared.b64 [%0], 1;" :: "r"(mbar) : "memory");
    __syncthreads();

    // phase A: TMA load (+ halo splat for the first quarter)
    if (tid == 0) {
        const int   nbytes = (quar == 0) ? TILE_T * 4 : XS_LEN * 4;
        const float* src   = (quar == 0) ? xrow : (xrow + t_base - HALO);
        uint32_t dst = (uint32_t)__cvta_generic_to_shared(
                           (quar == 0) ? (xs + HALO) : xs);
        asm volatile("mbarrier.arrive.expect_tx.shared.b64 _, [%0], %1;"
                     :: "r"(mbar), "r"(nbytes) : "memory");
        asm volatile(
            "cp.async.bulk.shared::cluster.global.mbarrier::complete_tx::bytes "
            "[%0], [%1], %2, [%3];"
            :: "r"(dst), "l"(src), "r"(nbytes), "r"(mbar) : "memory");
    }

    // constants overlap the DMA
    const float af = __ldg(&a[f]);
    const float wf = __ldg(&w[f]);
    const float p498 = ipowf(af, WIN);
    const float Cw = (1.0f - af) / (1.0f - p498) * wf;
    const float a10  = ipowf(af, 10);
    const float a20  = a10 * a10;
    const float a100 = ipowf(a20, 5);

    if (quar == 0) {
        const float x0v = __ldg(&xrow[0]);
        const float4 pad4 = make_float4(x0v, x0v, x0v, x0v);
        #pragma unroll
        for (int i = tid; i < HALO / 4; i += BLOCK)
            xs4[i] = pad4;   // disjoint from DMA destination
    }
    mbar_wait0(mbar);
    __syncthreads();   // splat + DMA visible to all

    // ---- B1: aligned chunk sums G_k = Horner20 over xs[20k..20k+19] ----
    if (tid < NG) {
        const int b4 = 5 * tid;
        const float4 q0 = xs4[b4];
        const float4 q1 = xs4[b4 + 1];
        const float4 q2 = xs4[b4 + 2];
        const float4 q3 = xs4[b4 + 3];
        const float4 q4 = xs4[b4 + 4];
        float pA = q0.x;
        pA = fmaf(af, pA, q0.y); pA = fmaf(af, pA, q0.z); pA = fmaf(af, pA, q0.w);
        pA = fmaf(af, pA, q1.x); pA = fmaf(af, pA, q1.y);
        pA = fmaf(af, pA, q1.z); pA = fmaf(af, pA, q1.w);
        pA = fmaf(af, pA, q2.x); pA = fmaf(af, pA, q2.y);
        float pB = q2.z;
        pB = fmaf(af, pB, q2.w);
        pB = fmaf(af, pB, q3.x); pB = fmaf(af, pB, q3.y);
        pB = fmaf(af, pB, q3.z); pB = fmaf(af, pB, q3.w);
        pB = fmaf(af, pB, q4.x); pB = fmaf(af, pB, q4.y);
        pB = fmaf(af, pB, q4.z); pB = fmaf(af, pB, q4.w);
        sG[tid] = fmaf(pA, a10, pB);
    }
    __syncthreads();

    // ---- B1.5: level-1 partials sP[j] = Horner(sG[j..j+4], a^20) ----
    if (tid < NP) {
        float p = sG[tid];
        p = fmaf(a20, p, sG[tid + 1]);
        p = fmaf(a20, p, sG[tid + 2]);
        p = fmaf(a20, p, sG[tid + 3]);
        p = fmaf(a20, p, sG[tid + 4]);
        sP[tid] = p;
    }
    __syncthreads();

    // ---- B2: level-2 combine + correction + sliding recurrence ----
    if (tid < NSUB) {
        // W = Horner(sP[tid], sP[tid+5], ..., sP[tid+20], base a^100)
        float W = sP[tid];
        W = fmaf(a100, W, sP[tid + 5]);
        W = fmaf(a100, W, sP[tid + 10]);
        W = fmaf(a100, W, sP[tid + 15]);
        W = fmaf(a100, W, sP[tid + 20]);

        const int q0i = 5 * tid;               // float4 index of window start
        float4* ys4 = (float4*)ys;
        float4 mA = xs4[q0i];                  // own-window quad 0
        // S = W - p498*(x[t0-499] + a*x[t0-500]) = W - p498*(mA.y + a*mA.x)
        float S = fmaf(-p498, fmaf(af, mA.x, mA.y), W);

        #pragma unroll
        for (int j = 0; j < 5; ++j) {
            const float4 mB = xs4[q0i + j + 1];
            const float4 xt = xs4[125 + q0i + j];   // xs[500 + 20i + 4j ..]
            float4 yv;
            yv.x = fabsf(fmaf(-Cw, S, xt.x));
            S = fmaf(af, S, fmaf(-p498, mA.z, xt.x));
            yv.y = fabsf(fmaf(-Cw, S, xt.y));
            S = fmaf(af, S, fmaf(-p498, mA.w, xt.y));
            yv.z = fabsf(fmaf(-Cw, S, xt.z));
            S = fmaf(af, S, fmaf(-p498, mB.x, xt.z));
            yv.w = fabsf(fmaf(-Cw, S, xt.w));
            S = fmaf(af, S, fmaf(-p498, mB.y, xt.w));
            ys4[q0i + j] = yv;
            mA = mB;
        }
    }
    __syncthreads();

    // ---- phase C: contiguous TMA store; release smem when read is done ----
    if (tid == 0) {
        uint32_t src = (uint32_t)__cvta_generic_to_shared(ys);
        asm volatile("fence.proxy.async.shared::cta;" ::: "memory");
        asm volatile("cp.async.bulk.global.shared::cta.bulk_group [%0], [%1], %2;"
                     :: "l"(orow), "r"(src), "r"(TILE_T * 4) : "memory");
        asm volatile("cp.async.bulk.commit_group;" ::: "memory");
        asm volatile("cp.async.bulk.wait_group.read 0;" ::: "memory");
    }
}

extern "C" void kernel_launch(void* const* d_in, const int* in_sizes, int n_in,
                              void* d_out, int out_size) {
    const float* x = (const float*)d_in[0];
    const float* a = (const float*)d_in[1];
    const float* w = (const float*)d_in[2];
    float* out = (float*)d_out;

    const int F = in_sizes[1];                 // 64
    const int rows = in_sizes[0] / T_LEN;      // 2048

    cudaFuncSetAttribute(willmore_kernel,
                         cudaFuncAttributeMaxDynamicSharedMemorySize, SMEM_BYTES);
    willmore_kernel<<<rows * 4, BLOCK, SMEM_BYTES>>>(x, a, w, out, F);
}